// round 1
// baseline (speedup 1.0000x reference)
#include <cuda_runtime.h>
#include <cstdint>

// Problem constants (fixed-shape problem): x_in [B,64,16384] f32, code_embedding [1024,64] f32
#define EMB      64
#define CODES    16384
#define NT_MAX   2048
#define TT       128          // tokens per shared-mem tile
#define QB       64           // queries (codes) per block
#define NTHREADS 256

// scratch: 0.5 * ||e_k||^2 per token
__device__ float g_halfE2[NT_MAX];

__global__ void e2_kernel(const float* __restrict__ e, int nt) {
    int t = blockIdx.x * blockDim.x + threadIdx.x;
    if (t < nt) {
        const float* row = e + (size_t)t * EMB;
        float s = 0.f;
#pragma unroll
        for (int j = 0; j < EMB; j++) s += row[j] * row[j];
        g_halfE2[t] = 0.5f * s;
    }
}

// Each block: one batch b, 64 consecutive codes (queries), scans all nt tokens.
// Thread microtile: 4 queries x 8 tokens (32 fp32 dot accumulators).
__global__ __launch_bounds__(NTHREADS) void vq_kernel(
    const float* __restrict__ x,      // [B, EMB, CODES]
    const float* __restrict__ e,      // [nt, EMB]
    float* __restrict__ xout,         // [B, EMB, CODES]
    float* __restrict__ idxout,       // [B, CODES] (as float)
    int nt)
{
    __shared__ float Xs[EMB][QB];         // [k][q]  16 KB
    __shared__ float Es[EMB][TT + 4];     // [k][t]  ~33.8 KB (stride 132 floats)
    __shared__ float hE2s[1024];          // 4 KB (nt == 1024 for this problem)
    __shared__ float redS[QB][16];
    __shared__ int   redI[QB][16];
    __shared__ int   qidx[QB];

    const int tid = threadIdx.x;
    const int b   = blockIdx.y;
    const int c0  = blockIdx.x * QB;
    const int tx  = tid & 15;   // query group: queries tx*4 .. tx*4+3
    const int ty  = tid >> 4;   // token group: tokens  ty*8 .. ty*8+7 (within tile)

    // ---- load X tile: Xs[k][q] = x[b][k][c0+q] (coalesced reads) ----
    const float* xb = x + (size_t)b * EMB * CODES + c0;
#pragma unroll
    for (int it = 0; it < (EMB * QB) / NTHREADS; ++it) {
        int idx = it * NTHREADS + tid;
        int k = idx >> 6;          // /QB
        int q = idx & (QB - 1);
        Xs[k][q] = xb[(size_t)k * CODES + q];
    }
    // ---- load halfE2 into smem ----
    for (int i = tid; i < nt; i += NTHREADS) hE2s[i] = g_halfE2[i];

    float best[4];
    int   bidx[4];
#pragma unroll
    for (int i = 0; i < 4; i++) { best[i] = -3.0e38f; bidx[i] = 0; }

    for (int t0 = 0; t0 < nt; t0 += TT) {
        __syncthreads();
        // ---- load E tile transposed: Es[k][t] = e[t0+t][k] (coalesced reads) ----
#pragma unroll
        for (int it = 0; it < (TT * EMB) / NTHREADS; ++it) {
            int idx = it * NTHREADS + tid;
            int t = idx >> 6;          // /EMB
            int k = idx & (EMB - 1);
            Es[k][t] = e[(size_t)(t0 + t) * EMB + k];
        }
        __syncthreads();

        float acc[4][8];
#pragma unroll
        for (int i = 0; i < 4; i++)
#pragma unroll
            for (int j = 0; j < 8; j++) acc[i][j] = 0.f;

#pragma unroll 8
        for (int k = 0; k < EMB; k++) {
            float4 xv = *(const float4*)&Xs[k][tx * 4];
            float4 e0 = *(const float4*)&Es[k][ty * 8];
            float4 e1 = *(const float4*)&Es[k][ty * 8 + 4];
            float xr[4] = {xv.x, xv.y, xv.z, xv.w};
            float er[8] = {e0.x, e0.y, e0.z, e0.w, e1.x, e1.y, e1.z, e1.w};
#pragma unroll
            for (int i = 0; i < 4; i++)
#pragma unroll
                for (int j = 0; j < 8; j++) acc[i][j] += xr[i] * er[j];
        }

        // fold -0.5*||e||^2 and track running argmax (ascending token order, strict >)
#pragma unroll
        for (int j = 0; j < 8; j++) {
            int tg = t0 + ty * 8 + j;
            float h = hE2s[tg];
#pragma unroll
            for (int i = 0; i < 4; i++) {
                float s = acc[i][j] - h;
                if (s > best[i]) { best[i] = s; bidx[i] = tg; }
            }
        }
    }

    // ---- cross-thread reduction: 16 token-groups per query ----
    __syncthreads();
#pragma unroll
    for (int i = 0; i < 4; i++) {
        redS[tx * 4 + i][ty] = best[i];
        redI[tx * 4 + i][ty] = bidx[i];
    }
    __syncthreads();

    if (tid < QB) {
        float bs = -3.0e38f;
        int   bi = 0;
#pragma unroll
        for (int g = 0; g < 16; g++) {
            float s = redS[tid][g];
            // NOTE: groups hold interleaved token ranges; exact float ties across
            // groups are measure-zero with continuous random data.
            if (s > bs) { bs = s; bi = redI[tid][g]; }
        }
        qidx[tid] = bi;
        idxout[(size_t)b * CODES + c0 + tid] = (float)bi;
    }
    __syncthreads();

    // ---- gather output: xout[b][j][c0+q] = e[qidx[q]][j] ----
#pragma unroll
    for (int it = 0; it < (EMB * QB) / NTHREADS; ++it) {
        int idx = it * NTHREADS + tid;
        int j = idx >> 6;          // emb dim
        int q = idx & (QB - 1);
        xout[(size_t)b * EMB * CODES + (size_t)j * CODES + c0 + q] =
            e[(size_t)qidx[q] * EMB + j];
    }
}

extern "C" void kernel_launch(void* const* d_in, const int* in_sizes, int n_in,
                              void* d_out, int out_size) {
    const float* x = (const float*)d_in[0];   // [B, 64, 16384]
    const float* e = (const float*)d_in[1];   // [nt, 64]

    int nt = in_sizes[1] / EMB;               // 1024
    int B  = in_sizes[0] / (EMB * CODES);     // 16

    float* xout   = (float*)d_out;
    float* idxout = xout + (size_t)B * EMB * CODES;

    e2_kernel<<<(nt + 255) / 256, 256>>>(e, nt);

    dim3 grid(CODES / QB, B);
    vq_kernel<<<grid, NTHREADS>>>(x, e, xout, idxout, nt);
}

// round 2
// speedup vs baseline: 1.0316x; 1.0316x over previous
#include <cuda_runtime.h>
#include <cstdint>

// x_in [B,64,16384] f32, code_embedding [1024,64] f32
#define EMB      64
#define CODES    16384
#define NT_MAX   2048
#define TT       128     // tokens per tile
#define QB       128     // queries per block
#define NTHREADS 256

typedef unsigned long long ull;

__device__ float g_halfE2[NT_MAX];

__global__ void e2_kernel(const float* __restrict__ e, int nt) {
    int t = blockIdx.x * blockDim.x + threadIdx.x;
    if (t < nt) {
        const float* row = e + (size_t)t * EMB;
        float s = 0.f;
#pragma unroll
        for (int j = 0; j < EMB; j++) s += row[j] * row[j];
        g_halfE2[t] = 0.5f * s;
    }
}

// Packed fp32x2 FMA (Blackwell FFMA2) + pack/unpack helpers
#define FMA2(d, a, b, c) \
    asm("fma.rn.f32x2 %0, %1, %2, %3;" : "=l"(d) : "l"(a), "l"(b), "l"(c))
#define PACK2(d, lo, hi) \
    asm("mov.b64 %0, {%1, %2};" : "=l"(d) : "f"(lo), "f"(hi))
#define UNPACK2(lo, hi, v) \
    asm("mov.b64 {%0, %1}, %2;" : "=f"(lo), "=f"(hi) : "l"(v))

// Dynamic smem layout (floats):
//   Xs   [64][128]            offset 0       (8192)
//   Es   [64][128] (swizzled) offset 8192    (8192)
//   hE2  [1024]               offset 16384   (1024)
//   redS [128][16]            offset 17408   (2048)
//   redI [128][16] (int)      offset 19456   (2048)
//   qidx [128]     (int)      offset 21504   (128)
#define SM_XS   0
#define SM_ES   8192
#define SM_HE2  16384
#define SM_REDS 17408
#define SM_REDI 19456
#define SM_QIDX 21504
#define SM_TOTAL_FLOATS 21632

// Each block: batch b, 128 consecutive codes. Thread microtile: 8 queries
// (4 f32x2 pairs) x 8 tokens. 16x16 thread grid over a 128q x 128t tile.
__global__ __launch_bounds__(NTHREADS, 2) void vq_kernel(
    const float* __restrict__ x,      // [B, EMB, CODES]
    const float* __restrict__ e,      // [nt, EMB]
    float* __restrict__ xout,         // [B, EMB, CODES]
    float* __restrict__ idxout,       // [B, CODES] (as float)
    int nt)
{
    extern __shared__ float sm[];
    float* Xs  = sm + SM_XS;
    float* Es  = sm + SM_ES;
    float* hE2 = sm + SM_HE2;
    float* redS = sm + SM_REDS;
    int*   redI = (int*)(sm + SM_REDI);
    int*   qidx = (int*)(sm + SM_QIDX);

    const int tid = threadIdx.x;
    const int b   = blockIdx.y;
    const int c0  = blockIdx.x * QB;
    const int tx  = tid & 15;    // query group: queries tx*8 .. tx*8+7
    const int ty  = tid >> 4;    // token group: tokens  ty*8 .. ty*8+7 in tile

    // ---- load X tile: Xs[k][q] = x[b][k][c0+q] (coalesced; conflict-free STS) ----
    const float* xb = x + (size_t)b * EMB * CODES + c0;
#pragma unroll
    for (int it = 0; it < (EMB * QB) / NTHREADS; ++it) {
        int idx = it * NTHREADS + tid;
        int q = idx & (QB - 1);
        int k = idx >> 7;
        Xs[k * QB + q] = xb[(size_t)k * CODES + q];
    }
    for (int i = tid; i < nt; i += NTHREADS) hE2[i] = g_halfE2[i];

    float best[8];
    int   bidx[8];
#pragma unroll
    for (int i = 0; i < 8; i++) { best[i] = -3.0e38f; bidx[i] = 0; }

    for (int t0 = 0; t0 < nt; t0 += TT) {
        __syncthreads();
        // ---- load E tile transposed + XOR swizzle on 16B chunks:
        // logical (k, t) stored at chunk p = (t>>2) ^ (k&7)
#pragma unroll
        for (int it = 0; it < (TT * EMB) / NTHREADS; ++it) {
            int idx = it * NTHREADS + tid;
            int k = idx & (EMB - 1);
            int t = idx >> 6;
            int p = (t >> 2) ^ (k & 7);
            Es[k * TT + (p << 2) + (t & 3)] = e[(size_t)(t0 + t) * EMB + k];
        }
        __syncthreads();

        ull acc[4][8];
#pragma unroll
        for (int i = 0; i < 4; i++)
#pragma unroll
            for (int j = 0; j < 8; j++) acc[i][j] = 0ULL;

#pragma unroll 4
        for (int k = 0; k < EMB; k++) {
            // 8 queries as 4 packed pairs via two LDS.128 (16B-aligned)
            const ulonglong2* xp =
                reinterpret_cast<const ulonglong2*>(&Xs[k * QB + tx * 8]);
            ulonglong2 xv0 = xp[0];
            ulonglong2 xv1 = xp[1];
            ull xq[4] = {xv0.x, xv0.y, xv1.x, xv1.y};

            // 8 tokens: two float4 chunks (swizzled), then duplicate each
            int sw = k & 7;
            const float4 e0 = *(const float4*)&Es[k * TT + (((ty * 2)     ^ sw) << 2)];
            const float4 e1 = *(const float4*)&Es[k * TT + (((ty * 2 + 1) ^ sw) << 2)];
            float ev[8] = {e0.x, e0.y, e0.z, e0.w, e1.x, e1.y, e1.z, e1.w};
            ull ed[8];
#pragma unroll
            for (int j = 0; j < 8; j++) PACK2(ed[j], ev[j], ev[j]);

#pragma unroll
            for (int i = 0; i < 4; i++)
#pragma unroll
                for (int j = 0; j < 8; j++)
                    FMA2(acc[i][j], xq[i], ed[j], acc[i][j]);
        }

        // fold -0.5*||e||^2, update running argmax (tokens ascending, strict >)
#pragma unroll
        for (int j = 0; j < 8; j++) {
            int tg = t0 + ty * 8 + j;
            float h = hE2[tg];
#pragma unroll
            for (int i = 0; i < 4; i++) {
                float lo, hi;
                UNPACK2(lo, hi, acc[i][j]);
                float s0 = lo - h;
                float s1 = hi - h;
                if (s0 > best[2 * i])     { best[2 * i]     = s0; bidx[2 * i]     = tg; }
                if (s1 > best[2 * i + 1]) { best[2 * i + 1] = s1; bidx[2 * i + 1] = tg; }
            }
        }
    }

    // ---- cross-thread reduction: 16 token-groups per query ----
    __syncthreads();
#pragma unroll
    for (int i = 0; i < 8; i++) {
        redS[(tx * 8 + i) * 16 + ty] = best[i];
        redI[(tx * 8 + i) * 16 + ty] = bidx[i];
    }
    __syncthreads();

    if (tid < QB) {
        float bs = -3.0e38f;
        int   bi = 0;
#pragma unroll
        for (int g = 0; g < 16; g++) {
            float s = redS[tid * 16 + g];
            // groups hold interleaved token ranges; exact float ties across
            // groups are measure-zero with continuous random data.
            if (s > bs) { bs = s; bi = redI[tid * 16 + g]; }
        }
        qidx[tid] = bi;
        idxout[(size_t)b * CODES + c0 + tid] = (float)bi;
    }
    __syncthreads();

    // ---- gather output: xout[b][j][c0+q] = e[qidx[q]][j] ----
#pragma unroll
    for (int it = 0; it < (EMB * QB) / NTHREADS; ++it) {
        int idx = it * NTHREADS + tid;
        int j = idx >> 7;
        int q = idx & (QB - 1);
        xout[(size_t)b * EMB * CODES + (size_t)j * CODES + c0 + q] =
            e[(size_t)qidx[q] * EMB + j];
    }
}

extern "C" void kernel_launch(void* const* d_in, const int* in_sizes, int n_in,
                              void* d_out, int out_size) {
    const float* x = (const float*)d_in[0];   // [B, 64, 16384]
    const float* e = (const float*)d_in[1];   // [nt, 64]

    int nt = in_sizes[1] / EMB;               // 1024
    int B  = in_sizes[0] / (EMB * CODES);     // 16

    float* xout   = (float*)d_out;
    float* idxout = xout + (size_t)B * EMB * CODES;

    e2_kernel<<<(nt + 255) / 256, 256>>>(e, nt);

    size_t smem_bytes = SM_TOTAL_FLOATS * sizeof(float);
    cudaFuncSetAttribute(vq_kernel, cudaFuncAttributeMaxDynamicSharedMemorySize,
                         (int)smem_bytes);

    dim3 grid(CODES / QB, B);
    vq_kernel<<<grid, NTHREADS, smem_bytes>>>(x, e, xout, idxout, nt);
}

// round 5
// speedup vs baseline: 1.4202x; 1.3767x over previous
#include <cuda_runtime.h>
#include <cstdint>

#define EMB      64
#define CODES    16384
#define NT       1024
#define TT       128
#define NTILES   (NT / TT)    // 8
#define QB       128
#define NTHREADS 256

// packed tf32 B fragments per tile: [split2][ks8][ns16][lane32][2] floats = 16384 floats (64KB)
__device__ float g_B[NTILES][16384];
__device__ float g_hE2[NT];

__device__ __forceinline__ uint32_t f2tf32(float v) {
    uint32_t r;
    asm("cvt.rna.tf32.f32 %0, %1;" : "=r"(r) : "f"(v));
    return r;
}

__device__ __forceinline__ void mma_tf32(float* d, uint4 a, uint2 b) {
    asm volatile(
        "mma.sync.aligned.m16n8k8.row.col.f32.tf32.tf32.f32 "
        "{%0,%1,%2,%3},{%4,%5,%6,%7},{%8,%9},{%0,%1,%2,%3};"
        : "+f"(d[0]), "+f"(d[1]), "+f"(d[2]), "+f"(d[3])
        : "r"(a.x), "r"(a.y), "r"(a.z), "r"(a.w), "r"(b.x), "r"(b.y));
}

#define CP_ASYNC16(dst, src) \
    asm volatile("cp.async.cg.shared.global [%0], [%1], 16;" :: "r"(dst), "l"(src))
#define CP_COMMIT()  asm volatile("cp.async.commit_group;" ::: "memory")
#define CP_WAIT(n)   asm volatile("cp.async.wait_group %0;" :: "n"(n) : "memory")

__device__ __forceinline__ uint32_t smem_u32(const void* p) {
    uint32_t a;
    asm("{ .reg .u64 t; cvta.to.shared.u64 t, %1; cvt.u32.u64 %0, t; }" : "=r"(a) : "l"(p));
    return a;
}

// ---------------- pre-kernel: split E into tf32 hi/lo fragments + halfE2 ----------------
__global__ void pre_kernel(const float* __restrict__ e) {
    const int tile = blockIdx.x;
    const int tid  = threadIdx.x;
    float* base = &g_B[tile][0];

    // fragment positions: ks8 * ns16 * lane32 = 4096, each holds (b0,b1) for 2 splits
    for (int p = tid; p < 4096; p += NTHREADS) {
        int lane = p & 31;
        int ns   = (p >> 5) & 15;
        int ks   = p >> 9;
        int tok  = tile * TT + ns * 8 + (lane >> 2);
        int k0   = ks * 8 + (lane & 3);
        float v0 = e[(size_t)tok * EMB + k0];
        float v1 = e[(size_t)tok * EMB + k0 + 4];
        uint32_t h0 = f2tf32(v0), h1 = f2tf32(v1);
        float l0 = v0 - __uint_as_float(h0);
        float l1 = v1 - __uint_as_float(h1);
        uint32_t L0 = f2tf32(l0), L1 = f2tf32(l1);
        int off = ks * 1024 + ns * 64 + lane * 2;          // split0
        base[off]     = __uint_as_float(h0);
        base[off + 1] = __uint_as_float(h1);
        base[8192 + off]     = __uint_as_float(L0);        // split1
        base[8192 + off + 1] = __uint_as_float(L1);
    }
    if (tid < TT) {
        int tok = tile * TT + tid;
        const float* row = e + (size_t)tok * EMB;
        float s = 0.f;
#pragma unroll
        for (int k = 0; k < EMB; k++) s += row[k] * row[k];
        g_hE2[tok] = 0.5f * s;
    }
}

// ---------------- SMEM layout (bytes) ----------------
#define SM_A     0          // 65536: [split2][mw4][ms2][ks8][lane32][4]f
#define SM_B0    65536      // 65536 per stage
#define SM_B1    131072
#define SM_HE2   196608     // 4096
#define SM_REDS  200704     // 128*2 floats
#define SM_REDI  201728     // 128*2 ints
#define SM_QIDX  202752     // 128 ints
#define SM_TOTAL 203264

__global__ __launch_bounds__(NTHREADS, 1) void vq_kernel(
    const float* __restrict__ x,      // [B, EMB, CODES]
    const float* __restrict__ e,      // [NT, EMB]
    float* __restrict__ xout,
    float* __restrict__ idxout)
{
    extern __shared__ uint8_t sm[];
    const uint32_t smb = smem_u32(sm);
    const int tid  = threadIdx.x;
    const int warp = tid >> 5;
    const int lane = tid & 31;
    const int mw   = warp >> 1;       // 0..3  (M: rows mw*32 .. mw*32+31)
    const int nw   = warp & 1;        // 0..1  (N: tokens nw*64 .. +63 within tile)
    const int b    = blockIdx.y;
    const int c0   = blockIdx.x * QB;

    float* hE2s = (float*)(sm + SM_HE2);
    for (int i = tid; i < NT; i += NTHREADS) hE2s[i] = g_hE2[i];

    // ---- pack A fragments: tf32 hi/lo of x[b][k][c0+r] in per-lane layout ----
    const float* xb = x + (size_t)b * EMB * CODES + c0;
    for (int p = tid; p < 2048; p += NTHREADS) {
        int ln = p & 31;
        int ks = (p >> 5) & 7;
        int ms = (p >> 8) & 1;
        int w  = p >> 9;
        int r  = w * 32 + ms * 16 + (ln >> 2);
        int k0 = ks * 8 + (ln & 3);
        float v00 = xb[(size_t)k0 * CODES + r];            // a0 (r,   k0)
        float v10 = xb[(size_t)k0 * CODES + r + 8];        // a1 (r+8, k0)
        float v01 = xb[(size_t)(k0 + 4) * CODES + r];      // a2 (r,   k0+4)
        float v11 = xb[(size_t)(k0 + 4) * CODES + r + 8];  // a3 (r+8, k0+4)
        uint32_t h0 = f2tf32(v00), h1 = f2tf32(v10), h2 = f2tf32(v01), h3 = f2tf32(v11);
        uint4 hi = {h0, h1, h2, h3};
        uint4 lo = {f2tf32(v00 - __uint_as_float(h0)),
                    f2tf32(v10 - __uint_as_float(h1)),
                    f2tf32(v01 - __uint_as_float(h2)),
                    f2tf32(v11 - __uint_as_float(h3))};
        int off = w * 8192 + ms * 4096 + ks * 512 + ln * 16;   // bytes
        *(uint4*)(sm + SM_A + off)         = hi;
        *(uint4*)(sm + SM_A + 32768 + off) = lo;
    }

    // ---- cp.async prologue: stage tiles 0 and 1 ----
#pragma unroll
    for (int st = 0; st < 2; st++) {
        const char* src = (const char*)&g_B[st][0];
        uint32_t dst = smb + SM_B0 + st * 65536;
#pragma unroll
        for (int it = 0; it < 16; it++) {
            int off = it * NTHREADS * 16 + tid * 16;
            CP_ASYNC16(dst + off, src + off);
        }
        CP_COMMIT();
    }

    float best[4];
    int   bidx[4];
#pragma unroll
    for (int s = 0; s < 4; s++) { best[s] = -3.0e38f; bidx[s] = 0; }

    const int pa[3] = {0, 0, 1};
    const int pb[3] = {0, 1, 0};

    for (int i = 0; i < NTILES; i++) {
        if (i < NTILES - 2) { CP_WAIT(1); } else { CP_WAIT(0); }
        __syncthreads();

        const uint32_t sb = smb + SM_B0 + (uint32_t)(i & 1) * 65536u;
        float acc[64];
#pragma unroll
        for (int z = 0; z < 64; z++) acc[z] = 0.f;

#pragma unroll
        for (int prod = 0; prod < 3; prod++) {
            const uint32_t abase = smb + SM_A + (uint32_t)pa[prod] * 32768u
                                 + (uint32_t)mw * 8192u + (uint32_t)lane * 16u;
            const uint32_t bbase = sb + (uint32_t)pb[prod] * 32768u
                                 + (uint32_t)(nw * 8) * 256u + (uint32_t)lane * 8u;
#pragma unroll
            for (int ks = 0; ks < 8; ks++) {
                uint4 a0, a1;
                asm volatile("ld.shared.v4.b32 {%0,%1,%2,%3}, [%4];"
                    : "=r"(a0.x), "=r"(a0.y), "=r"(a0.z), "=r"(a0.w)
                    : "r"(abase + ks * 512u));
                asm volatile("ld.shared.v4.b32 {%0,%1,%2,%3}, [%4];"
                    : "=r"(a1.x), "=r"(a1.y), "=r"(a1.z), "=r"(a1.w)
                    : "r"(abase + 4096u + ks * 512u));
                uint2 bv[8];
#pragma unroll
                for (int n = 0; n < 8; n++) {
                    asm volatile("ld.shared.v2.b32 {%0,%1}, [%2];"
                        : "=r"(bv[n].x), "=r"(bv[n].y)
                        : "r"(bbase + ks * 4096u + n * 256u));
                }
#pragma unroll
                for (int n = 0; n < 8; n++) {
                    mma_tf32(&acc[(0 * 8 + n) * 4], a0, bv[n]);
                    mma_tf32(&acc[(1 * 8 + n) * 4], a1, bv[n]);
                }
            }
        }

        // ---- epilogue: subtract halfE2, running argmax ----
#pragma unroll
        for (int ms = 0; ms < 2; ms++)
#pragma unroll
            for (int n = 0; n < 8; n++) {
                int tokb = i * TT + (nw * 8 + n) * 8 + (lane & 3) * 2;
                const float* d = &acc[(ms * 8 + n) * 4];
#pragma unroll
                for (int j = 0; j < 4; j++) {
                    int tok = tokb + (j & 1);
                    float v = d[j] - hE2s[tok];
                    int s = ms * 2 + (j >> 1);
                    if (v > best[s]) { best[s] = v; bidx[s] = tok; }
                }
            }

        __syncthreads();   // everyone done reading stage before refill
        if (i + 2 < NTILES) {
            const char* src = (const char*)&g_B[i + 2][0];
            uint32_t dst = smb + SM_B0 + (uint32_t)(i & 1) * 65536u;
#pragma unroll
            for (int it = 0; it < 16; it++) {
                int off = it * NTHREADS * 16 + tid * 16;
                CP_ASYNC16(dst + off, src + off);
            }
            CP_COMMIT();
        }
    }

    // ---- merge across the 4 lanes sharing each row (lane^1, lane^2) ----
#pragma unroll
    for (int s = 0; s < 4; s++) {
#pragma unroll
        for (int off = 1; off <= 2; off <<= 1) {
            float os = __shfl_xor_sync(0xffffffffu, best[s], off);
            int   oi = __shfl_xor_sync(0xffffffffu, bidx[s], off);
            if (os > best[s] || (os == best[s] && oi < bidx[s])) {
                best[s] = os; bidx[s] = oi;
            }
        }
    }

    float* REDS = (float*)(sm + SM_REDS);
    int*   REDI = (int*)(sm + SM_REDI);
    int*   QIDX = (int*)(sm + SM_QIDX);
    if ((lane & 3) == 0) {
#pragma unroll
        for (int s = 0; s < 4; s++) {
            int row = mw * 32 + (s >> 1) * 16 + (lane >> 2) + (s & 1) * 8;
            REDS[row * 2 + nw] = best[s];
            REDI[row * 2 + nw] = bidx[s];
        }
    }
    __syncthreads();

    if (tid < QB) {
        float s0 = REDS[tid * 2], s1 = REDS[tid * 2 + 1];
        int   i0 = REDI[tid * 2], i1 = REDI[tid * 2 + 1];
        int bi = (s1 > s0 || (s1 == s0 && i1 < i0)) ? i1 : i0;
        QIDX[tid] = bi;
        idxout[(size_t)b * CODES + c0 + tid] = (float)bi;
    }
    __syncthreads();

    // ---- gather x_out ----
#pragma unroll
    for (int it = 0; it < (EMB * QB) / NTHREADS; ++it) {
        int idx = it * NTHREADS + tid;
        int q = idx & (QB - 1);
        int j = idx >> 7;
        xout[(size_t)b * EMB * CODES + (size_t)j * CODES + c0 + q] =
            e[(size_t)QIDX[q] * EMB + j];
    }
}

extern "C" void kernel_launch(void* const* d_in, const int* in_sizes, int n_in,
                              void* d_out, int out_size) {
    const float* x = (const float*)d_in[0];   // [16, 64, 16384]
    const float* e = (const float*)d_in[1];   // [1024, 64]
    int B = in_sizes[0] / (EMB * CODES);

    float* xout   = (float*)d_out;
    float* idxout = xout + (size_t)B * EMB * CODES;

    pre_kernel<<<NTILES, NTHREADS>>>(e);

    cudaFuncSetAttribute(vq_kernel, cudaFuncAttributeMaxDynamicSharedMemorySize, SM_TOTAL);
    dim3 grid(CODES / QB, B);
    vq_kernel<<<grid, NTHREADS, SM_TOTAL>>>(x, e, xout, idxout);
}